// round 8
// baseline (speedup 1.0000x reference)
#include <cuda_runtime.h>
#include <cstdint>

#define NH    16
#define DK    64
#define BATCH 2
#define SEQ   2048
#define DEMB  1024
#define MTOT  (BATCH*SEQ)   // 4096

// Scratch (allocation-free: device globals)
// g_Q/g_K/g_V hold tf32-PRE-ROUNDED floats (rounded in gemm epilogue);
// g_Q additionally pre-scaled by 0.125*log2(e).
__device__ float g_Q[BATCH*NH*SEQ*DK];
__device__ float g_K[BATCH*NH*SEQ*DK];
__device__ float g_V[BATCH*NH*SEQ*DK];
__device__ float g_C[MTOT*DEMB];         // ctx, [b,s,h,dk] == row-major [4096,1024]

// ---------------------------------------------------------------------------
// helpers
// ---------------------------------------------------------------------------
__device__ __forceinline__ uint32_t smem_u32(const void* p) {
    uint32_t a;
    asm("{ .reg .u64 t; cvta.to.shared.u64 t, %1; cvt.u32.u64 %0, t; }"
        : "=r"(a) : "l"(p));
    return a;
}
__device__ __forceinline__ void cp16(uint32_t dst, const void* src) {
    asm volatile("cp.async.cg.shared.global [%0], [%1], 16;"
                 :: "r"(dst), "l"(src) : "memory");
}
#define CP_COMMIT() asm volatile("cp.async.commit_group;" ::: "memory")
#define CP_WAIT(n)  asm volatile("cp.async.wait_group %0;" :: "n"(n) : "memory")

__device__ __forceinline__ float ex2f(float x) {
    float r; asm("ex2.approx.ftz.f32 %0, %1;" : "=f"(r) : "f"(x)); return r;
}
__device__ __forceinline__ uint32_t cvt_tf32(float x) {
    uint32_t r; asm("cvt.rna.tf32.f32 %0, %1;" : "=r"(r) : "f"(x)); return r;
}
__device__ __forceinline__ void mma_tf32(float* d, const uint32_t* a, const uint32_t* b) {
    asm volatile("mma.sync.aligned.m16n8k8.row.col.f32.tf32.tf32.f32 "
        "{%0,%1,%2,%3}, {%4,%5,%6,%7}, {%8,%9}, {%0,%1,%2,%3};"
        : "+f"(d[0]), "+f"(d[1]), "+f"(d[2]), "+f"(d[3])
        : "r"(a[0]), "r"(a[1]), "r"(a[2]), "r"(a[3]), "r"(b[0]), "r"(b[1]));
}

// ===========================================================================
// tf32 mma.sync GEMM (unchanged).  MODE 1 epilogue tf32-pre-rounds output.
// ===========================================================================
#define GPAD 36
#define GSTAGE (2 * 128 * GPAD)
#define GSMEM  (2 * GSTAGE * 4)

template<int MODE>
__global__ void __launch_bounds__(128) gemm_tc(const float* __restrict__ A,
                                               const float* __restrict__ Bm,
                                               float* __restrict__ C,
                                               float cscale)
{
    extern __shared__ float gs[];
    const int tid  = threadIdx.x;
    const int lane = tid & 31;
    const int wid  = tid >> 5;
    const int wm   = (wid & 1) * 64;
    const int wn   = (wid >> 1) * 64;
    const int m0   = blockIdx.y * 128;
    const int n0   = blockIdx.x * 128;
    const uint32_t sb = smem_u32(gs);

#define STAGE_LOAD(cc, ss) do {                                              \
    _Pragma("unroll")                                                        \
    for (int i = 0; i < 16; i++) {                                           \
        int f   = tid + 128 * i;                                             \
        int isB = f >> 10;                                                   \
        int g   = f & 1023;                                                  \
        int row = g >> 3;                                                    \
        int cir = g & 7;                                                     \
        const float* src = (isB ? Bm + (size_t)(n0 + row) * DEMB             \
                                : A  + (size_t)(m0 + row) * DEMB)            \
                           + (cc) * 32 + cir * 4;                            \
        uint32_t dst = sb + ((ss) * GSTAGE + isB * (128 * GPAD)              \
                             + row * GPAD) * 4 + cir * 16;                   \
        cp16(dst, src);                                                      \
    }                                                                        \
} while (0)

    STAGE_LOAD(0, 0); CP_COMMIT();
    STAGE_LOAD(1, 1); CP_COMMIT();

    float acc[4][8][4];
#pragma unroll
    for (int mi = 0; mi < 4; mi++)
#pragma unroll
        for (int ni = 0; ni < 8; ni++)
#pragma unroll
            for (int j = 0; j < 4; j++) acc[mi][ni][j] = 0.f;

    const int r4 = lane >> 2;
    const int c4 = lane & 3;

    for (int c = 0; c < 32; c++) {
        CP_WAIT(1);
        __syncthreads();
        const float* As = gs + (c & 1) * GSTAGE;
        const float* Bs = As + 128 * GPAD;

#pragma unroll
        for (int k8 = 0; k8 < 4; k8++) {
            const int kb = k8 * 8 + c4;
            uint32_t a[4][4], b[8][2];
#pragma unroll
            for (int mi = 0; mi < 4; mi++) {
                const int r = wm + mi * 16 + r4;
                a[mi][0] = cvt_tf32(As[r * GPAD + kb]);
                a[mi][1] = cvt_tf32(As[(r + 8) * GPAD + kb]);
                a[mi][2] = cvt_tf32(As[r * GPAD + kb + 4]);
                a[mi][3] = cvt_tf32(As[(r + 8) * GPAD + kb + 4]);
            }
#pragma unroll
            for (int ni = 0; ni < 8; ni++) {
                const int cn = wn + ni * 8 + r4;
                b[ni][0] = cvt_tf32(Bs[cn * GPAD + kb]);
                b[ni][1] = cvt_tf32(Bs[cn * GPAD + kb + 4]);
            }
#pragma unroll
            for (int mi = 0; mi < 4; mi++)
#pragma unroll
                for (int ni = 0; ni < 8; ni++)
                    mma_tf32(acc[mi][ni], a[mi], b[ni]);
        }
        __syncthreads();
        if (c + 2 < 32) STAGE_LOAD(c + 2, c & 1);
        CP_COMMIT();
    }

    const int c2 = (lane & 3) * 2;
#pragma unroll
    for (int mi = 0; mi < 4; mi++) {
#pragma unroll
        for (int ni = 0; ni < 8; ni++) {
            const int m = m0 + wm + mi * 16 + r4;
            const int n = n0 + wn + ni * 8 + c2;
#pragma unroll
            for (int half = 0; half < 2; half++) {
                const int mm = m + half * 8;
                float2 v = make_float2(acc[mi][ni][2*half]   * cscale,
                                       acc[mi][ni][2*half+1] * cscale);
                if (MODE == 0) {
                    *(float2*)&C[(size_t)mm * DEMB + n] = v;
                } else {
                    v.x = __uint_as_float(cvt_tf32(v.x));   // pre-round for attn
                    v.y = __uint_as_float(cvt_tf32(v.y));
                    const int b  = mm >> 11;
                    const int s  = mm & (SEQ - 1);
                    const int h  = n >> 6;
                    const int dk = n & 63;
                    *(float2*)&C[(((size_t)(b * NH + h) * SEQ + s) << 6) + dk] = v;
                }
            }
        }
    }
#undef STAGE_LOAD
}

// ===========================================================================
// Tensor-core attention v3: 512 threads / 16 warps (was 256/8).
//  - Same q-tile 128, same smem layouts (all LDS patterns conflict-free).
//  - Score: warp = (mw: m32, kq: k-quarter of 32 rows) -> 2m16 x 4n8 x 8k8.
//  - AV:    warp = (mw: m32, dq: 16-wide d slice)      -> 2m16 x 2n8 x 16k8.
//  - rsum: 4 k-quarter partials combined via 512-float smem scratch at end.
//  Rationale: round-7 profile latency-bound (tensor 41%, L1 48%, issue 35%,
//  occ 12.5%); doubling warps/SMSP converts exposed latency into pipe time.
// ===========================================================================
#define CLIP2 7.2134752044448169f            // 5 * log2(e)
#define PK 68
#define PV 72
#define PP 132
#define AOFF_Q  0
#define AOFF_K0 (128*PK)
#define AOFF_K1 (2*128*PK)
#define AOFF_V  (3*128*PK)
#define AOFF_P  (3*128*PK + 128*PV)
#define ATT_SMEM ((AOFF_P + 128*PP)*4)       // 208896 bytes

__device__ __forceinline__ uint32_t f2b(float x) { return __float_as_uint(x); }

__global__ void __launch_bounds__(512, 1) attn_tc()
{
    extern __shared__ float smf[];
    const uint32_t sb = smem_u32(smf);
    const int tid  = threadIdx.x;
    const int wid  = tid >> 5;
    const int lane = tid & 31;
    const int g    = lane >> 2;        // row-in-8 group
    const int tq   = lane & 3;         // quad index
    const int mw   = wid & 3;          // m32 block: rows mw*32 .. +31
    const int kq   = wid >> 2;         // score: k-quarter | AV: d-slice (0..3)
    const int bh   = blockIdx.y;
    const int q0   = blockIdx.x << 7;

    const float* Qg = g_Q + (size_t)bh * (SEQ * DK) + (size_t)q0 * DK;
    const float* Kg = g_K + (size_t)bh * (SEQ * DK);
    const float* Vg = g_V + (size_t)bh * (SEQ * DK);

    // async-load Q tile and K tile 0
#pragma unroll
    for (int i = 0; i < 4; i++) {
        int f = tid + 512 * i;
        int r = f >> 4;
        int c = (f & 15) << 2;
        cp16(sb + (AOFF_Q  + r * PK + c) * 4, Qg + (size_t)r * DK + c);
        cp16(sb + (AOFF_K0 + r * PK + c) * 4, Kg + (size_t)r * DK + c);
    }
    CP_COMMIT();

    float acc[2][2][4];
#pragma unroll
    for (int mi = 0; mi < 2; mi++)
#pragma unroll
        for (int ni = 0; ni < 2; ni++)
#pragma unroll
            for (int j = 0; j < 4; j++) acc[mi][ni][j] = 0.f;
    float rs[4] = {0.f, 0.f, 0.f, 0.f};

    const float* Qw  = smf + AOFF_Q + (mw * 32) * PK;
    float*       Pw  = smf + AOFF_P + (mw * 32) * PP;
    const float* Vsm = smf + AOFF_V;

    for (int t = 0; t < SEQ / 128; t++) {
        // prefetch V_t
        const float* Vt = Vg + (size_t)(t << 7) * DK;
#pragma unroll
        for (int i = 0; i < 4; i++) {
            int f = tid + 512 * i;
            int r = f >> 4;
            int c = (f & 15) << 2;
            cp16(sb + (AOFF_V + r * PV + c) * 4, Vt + (size_t)r * DK + c);
        }
        CP_COMMIT();
        // prefetch K_{t+1}
        if (t + 1 < SEQ / 128) {
            const float* Kt = Kg + (size_t)((t + 1) << 7) * DK;
            const int ko = ((t + 1) & 1) ? AOFF_K1 : AOFF_K0;
#pragma unroll
            for (int i = 0; i < 4; i++) {
                int f = tid + 512 * i;
                int r = f >> 4;
                int c = (f & 15) << 2;
                cp16(sb + (ko + r * PK + c) * 4, Kt + (size_t)r * DK + c);
            }
        }
        CP_COMMIT();

        CP_WAIT(2);                 // K_t (and Q) resident
        __syncthreads();

        // this warp's 32-row quarter of the K tile
        const float* Kb = smf + ((t & 1) ? AOFF_K1 : AOFF_K0) + (kq * 32) * PK;

        // ---- scores: 2 m16 x 4 n8 x 8 k8 ----
        float sc[2][4][4];
#pragma unroll
        for (int mi = 0; mi < 2; mi++)
#pragma unroll
            for (int ni = 0; ni < 4; ni++)
#pragma unroll
                for (int j = 0; j < 4; j++) sc[mi][ni][j] = 0.f;

#pragma unroll 2
        for (int k8 = 0; k8 < 8; k8++) {
            const int kc = tq + 8 * k8;
            uint32_t a[2][4];
#pragma unroll
            for (int mi = 0; mi < 2; mi++) {
                const float* Qr = Qw + (mi * 16 + g) * PK + kc;
                a[mi][0] = f2b(Qr[0]);
                a[mi][1] = f2b(Qr[8 * PK]);
                a[mi][2] = f2b(Qr[4]);
                a[mi][3] = f2b(Qr[8 * PK + 4]);
            }
#pragma unroll
            for (int ni = 0; ni < 4; ni++) {
                uint32_t b[2];
                const float* Kr = Kb + (8 * ni + g) * PK + kc;
                b[0] = f2b(Kr[0]);
                b[1] = f2b(Kr[4]);
                mma_tf32(sc[0][ni], a[0], b);
                mma_tf32(sc[1][ni], a[1], b);
            }
        }

        // ---- clip + 2^x + tf32-round, stage P cols [kq*32, kq*32+32) ----
#pragma unroll
        for (int mi = 0; mi < 2; mi++) {
            float* Pm = Pw + (mi * 16 + g) * PP + kq * 32 + 2 * tq;
#pragma unroll
            for (int ni = 0; ni < 4; ni++) {
                float e0 = __uint_as_float(cvt_tf32(ex2f(fminf(fmaxf(sc[mi][ni][0], -CLIP2), CLIP2))));
                float e1 = __uint_as_float(cvt_tf32(ex2f(fminf(fmaxf(sc[mi][ni][1], -CLIP2), CLIP2))));
                float e2 = __uint_as_float(cvt_tf32(ex2f(fminf(fmaxf(sc[mi][ni][2], -CLIP2), CLIP2))));
                float e3 = __uint_as_float(cvt_tf32(ex2f(fminf(fmaxf(sc[mi][ni][3], -CLIP2), CLIP2))));
                rs[2 * mi]     += e0 + e1;
                rs[2 * mi + 1] += e2 + e3;
                *(float2*)&Pm[ni * 8]          = make_float2(e0, e1);
                *(float2*)&Pm[ni * 8 + 8 * PP] = make_float2(e2, e3);
            }
        }

        CP_WAIT(1);                 // V_t resident
        __syncthreads();            // all P quarters + V visible

        // ---- AV: 2 m16 x 2 n8 (d-slice kq) x 16 k8 ----
        const int dcol = kq * 16;
#pragma unroll 2
        for (int k8 = 0; k8 < 16; k8++) {
            const int kp = tq + 8 * k8;
            uint32_t a[2][4];
#pragma unroll
            for (int mi = 0; mi < 2; mi++) {
                const float* Pr = Pw + (mi * 16 + g) * PP + kp;
                a[mi][0] = f2b(Pr[0]);
                a[mi][1] = f2b(Pr[8 * PP]);
                a[mi][2] = f2b(Pr[4]);
                a[mi][3] = f2b(Pr[8 * PP + 4]);
            }
#pragma unroll
            for (int ni = 0; ni < 2; ni++) {
                uint32_t b[2];
                b[0] = f2b(Vsm[kp * PV + dcol + 8 * ni + g]);
                b[1] = f2b(Vsm[(kp + 4) * PV + dcol + 8 * ni + g]);
                mma_tf32(acc[0][ni], a[0], b);
                mma_tf32(acc[1][ni], a[1], b);
            }
        }
        __syncthreads();            // P / V reusable next tile
    }

    // ---- rsum: quad reduce, then combine the four kq quarters via smem ----
#pragma unroll
    for (int j = 0; j < 4; j++) {
        rs[j] += __shfl_xor_sync(0xffffffffu, rs[j], 1);
        rs[j] += __shfl_xor_sync(0xffffffffu, rs[j], 2);
    }
    float* Rsum = smf + AOFF_P;     // 512 floats scratch (P no longer needed)
    if (tq == 0) {
        Rsum[kq * 128 + mw * 32 + g]          = rs[0];
        Rsum[kq * 128 + mw * 32 + g + 8]      = rs[1];
        Rsum[kq * 128 + mw * 32 + 16 + g]     = rs[2];
        Rsum[kq * 128 + mw * 32 + 16 + g + 8] = rs[3];
    }
    __syncthreads();

    // ---- normalize + write ctx in [b,s,h,dk] layout ----
    const int bb = bh >> 4;
    const int h  = bh & 15;
#pragma unroll
    for (int mi = 0; mi < 2; mi++) {
        const int r0 = mw * 32 + mi * 16 + g;
        const float inv0 = 1.f / (Rsum[r0] + Rsum[128 + r0] +
                                  Rsum[256 + r0] + Rsum[384 + r0]);
        const float inv1 = 1.f / (Rsum[r0 + 8] + Rsum[128 + r0 + 8] +
                                  Rsum[256 + r0 + 8] + Rsum[384 + r0 + 8]);
        float* C0 = g_C + (((size_t)(bb * SEQ + q0 + r0) * NH + h) << 6) + kq * 16;
        float* C1 = C0 + ((size_t)8 * NH << 6);
#pragma unroll
        for (int ni = 0; ni < 2; ni++) {
            *(float2*)&C0[ni * 8 + 2 * tq] = make_float2(acc[mi][ni][0] * inv0,
                                                         acc[mi][ni][1] * inv0);
            *(float2*)&C1[ni * 8 + 2 * tq] = make_float2(acc[mi][ni][2] * inv1,
                                                         acc[mi][ni][3] * inv1);
        }
    }
}

// ===========================================================================
extern "C" void kernel_launch(void* const* d_in, const int* in_sizes, int n_in,
                              void* d_out, int out_size)
{
    const float* X  = (const float*)d_in[0];
    const float* Wq = (const float*)d_in[1];
    const float* Wk = (const float*)d_in[2];
    const float* Wv = (const float*)d_in[3];
    const float* Wo = (const float*)d_in[4];
    float* out = (float*)d_out;

    float *pQ, *pK, *pV, *pC;
    cudaGetSymbolAddress((void**)&pQ, g_Q);
    cudaGetSymbolAddress((void**)&pK, g_K);
    cudaGetSymbolAddress((void**)&pV, g_V);
    cudaGetSymbolAddress((void**)&pC, g_C);

    cudaFuncSetAttribute(gemm_tc<0>, cudaFuncAttributeMaxDynamicSharedMemorySize, GSMEM);
    cudaFuncSetAttribute(gemm_tc<1>, cudaFuncAttributeMaxDynamicSharedMemorySize, GSMEM);
    cudaFuncSetAttribute(attn_tc,    cudaFuncAttributeMaxDynamicSharedMemorySize, ATT_SMEM);

    dim3 gg(DEMB / 128, MTOT / 128);   // (8, 32)
    // Q projection carries 1/sqrt(Dk) * log2(e) so attention can use ex2
    gemm_tc<1><<<gg, 128, GSMEM>>>(X, Wq, pQ, 0.18033688011112042592f);
    gemm_tc<1><<<gg, 128, GSMEM>>>(X, Wk, pK, 1.0f);
    gemm_tc<1><<<gg, 128, GSMEM>>>(X, Wv, pV, 1.0f);

    attn_tc<<<dim3(SEQ / 128, BATCH * NH), 512, ATT_SMEM>>>();

    gemm_tc<0><<<gg, 128, GSMEM>>>(pC, Wo, out, 1.0f);
}

// round 9
// speedup vs baseline: 1.0769x; 1.0769x over previous
#include <cuda_runtime.h>
#include <cstdint>

#define NH    16
#define DK    64
#define BATCH 2
#define SEQ   2048
#define DEMB  1024
#define MTOT  (BATCH*SEQ)   // 4096

// Scratch (allocation-free: device globals)
// g_Q/g_K/g_V hold tf32-PRE-ROUNDED floats (rounded in gemm epilogue);
// g_Q additionally pre-scaled by 0.125*log2(e).
__device__ float g_Q[BATCH*NH*SEQ*DK];
__device__ float g_K[BATCH*NH*SEQ*DK];
__device__ float g_V[BATCH*NH*SEQ*DK];
__device__ float g_C[MTOT*DEMB];         // ctx, [b,s,h,dk] == row-major [4096,1024]

// ---------------------------------------------------------------------------
// helpers
// ---------------------------------------------------------------------------
__device__ __forceinline__ uint32_t smem_u32(const void* p) {
    uint32_t a;
    asm("{ .reg .u64 t; cvta.to.shared.u64 t, %1; cvt.u32.u64 %0, t; }"
        : "=r"(a) : "l"(p));
    return a;
}
__device__ __forceinline__ void cp16(uint32_t dst, const void* src) {
    asm volatile("cp.async.cg.shared.global [%0], [%1], 16;"
                 :: "r"(dst), "l"(src) : "memory");
}
#define CP_COMMIT() asm volatile("cp.async.commit_group;" ::: "memory")
#define CP_WAIT(n)  asm volatile("cp.async.wait_group %0;" :: "n"(n) : "memory")

__device__ __forceinline__ float ex2f(float x) {
    float r; asm("ex2.approx.ftz.f32 %0, %1;" : "=f"(r) : "f"(x)); return r;
}
__device__ __forceinline__ uint32_t cvt_tf32(float x) {
    uint32_t r; asm("cvt.rna.tf32.f32 %0, %1;" : "=r"(r) : "f"(x)); return r;
}
__device__ __forceinline__ void mma_tf32(float* d, const uint32_t* a, const uint32_t* b) {
    asm volatile("mma.sync.aligned.m16n8k8.row.col.f32.tf32.tf32.f32 "
        "{%0,%1,%2,%3}, {%4,%5,%6,%7}, {%8,%9}, {%0,%1,%2,%3};"
        : "+f"(d[0]), "+f"(d[1]), "+f"(d[2]), "+f"(d[3])
        : "r"(a[0]), "r"(a[1]), "r"(a[2]), "r"(a[3]), "r"(b[0]), "r"(b[1]));
}
__device__ __forceinline__ uint32_t f2b(float x) { return __float_as_uint(x); }

// ===========================================================================
// tf32 mma.sync GEMM core (128x128 tile, 128 thr, 2-stage cp.async).
// GEMM_BODY computes acc[4][8][4] for tile (m0,n0) from A and Bm.
// ===========================================================================
#define GPAD 36
#define GSTAGE (2 * 128 * GPAD)
#define GSMEM  (2 * GSTAGE * 4)

#define STAGE_LOAD(cc, ss) do {                                              \
    _Pragma("unroll")                                                        \
    for (int i = 0; i < 16; i++) {                                           \
        int f   = tid + 128 * i;                                             \
        int isB = f >> 10;                                                   \
        int gi  = f & 1023;                                                  \
        int row = gi >> 3;                                                   \
        int cir = gi & 7;                                                    \
        const float* src = (isB ? Bm + (size_t)(n0 + row) * DEMB             \
                                : A  + (size_t)(m0 + row) * DEMB)            \
                           + (cc) * 32 + cir * 4;                            \
        uint32_t dst = sb + ((ss) * GSTAGE + isB * (128 * GPAD)              \
                             + row * GPAD) * 4 + cir * 16;                   \
        cp16(dst, src);                                                      \
    }                                                                        \
} while (0)

#define GEMM_BODY                                                            \
    STAGE_LOAD(0, 0); CP_COMMIT();                                           \
    STAGE_LOAD(1, 1); CP_COMMIT();                                           \
    float acc[4][8][4];                                                      \
    _Pragma("unroll")                                                        \
    for (int mi = 0; mi < 4; mi++)                                           \
        _Pragma("unroll")                                                    \
        for (int ni = 0; ni < 8; ni++)                                       \
            _Pragma("unroll")                                                \
            for (int j = 0; j < 4; j++) acc[mi][ni][j] = 0.f;                \
    const int r4 = lane >> 2;                                                \
    const int c4 = lane & 3;                                                 \
    for (int c = 0; c < 32; c++) {                                           \
        CP_WAIT(1);                                                          \
        __syncthreads();                                                     \
        const float* As = gs + (c & 1) * GSTAGE;                             \
        const float* Bs = As + 128 * GPAD;                                   \
        _Pragma("unroll")                                                    \
        for (int k8 = 0; k8 < 4; k8++) {                                     \
            const int kb = k8 * 8 + c4;                                      \
            uint32_t a[4][4], b[8][2];                                       \
            _Pragma("unroll")                                                \
            for (int mi = 0; mi < 4; mi++) {                                 \
                const int r = wm + mi * 16 + r4;                             \
                a[mi][0] = cvt_tf32(As[r * GPAD + kb]);                      \
                a[mi][1] = cvt_tf32(As[(r + 8) * GPAD + kb]);                \
                a[mi][2] = cvt_tf32(As[r * GPAD + kb + 4]);                  \
                a[mi][3] = cvt_tf32(As[(r + 8) * GPAD + kb + 4]);            \
            }                                                                \
            _Pragma("unroll")                                                \
            for (int ni = 0; ni < 8; ni++) {                                 \
                const int cn = wn + ni * 8 + r4;                             \
                b[ni][0] = cvt_tf32(Bs[cn * GPAD + kb]);                     \
                b[ni][1] = cvt_tf32(Bs[cn * GPAD + kb + 4]);                 \
            }                                                                \
            _Pragma("unroll")                                                \
            for (int mi = 0; mi < 4; mi++)                                   \
                _Pragma("unroll")                                            \
                for (int ni = 0; ni < 8; ni++)                               \
                    mma_tf32(acc[mi][ni], a[mi], b[ni]);                     \
        }                                                                    \
        __syncthreads();                                                     \
        if (c + 2 < 32) STAGE_LOAD(c + 2, c & 1);                            \
        CP_COMMIT();                                                         \
    }

// ---- fused QKV projection: grid (24, 32); mat = blockIdx.x>>3 -----------
__global__ void __launch_bounds__(128) gemm_qkv(const float* __restrict__ A,
                                                const float* __restrict__ Wq,
                                                const float* __restrict__ Wk,
                                                const float* __restrict__ Wv,
                                                float* __restrict__ Cq,
                                                float* __restrict__ Ck,
                                                float* __restrict__ Cv,
                                                float qscale)
{
    extern __shared__ float gs[];
    const int tid  = threadIdx.x;
    const int lane = tid & 31;
    const int wid  = tid >> 5;
    const int wm   = (wid & 1) * 64;
    const int wn   = (wid >> 1) * 64;
    const int m0   = blockIdx.y * 128;
    const int mat  = blockIdx.x >> 3;
    const int n0   = (blockIdx.x & 7) * 128;
    const uint32_t sb = smem_u32(gs);

    const float* Bm = (mat == 0) ? Wq : (mat == 1) ? Wk : Wv;
    float*       C  = (mat == 0) ? Cq : (mat == 1) ? Ck : Cv;
    const float  cscale = (mat == 0) ? qscale : 1.0f;

    GEMM_BODY

    const int c2 = (lane & 3) * 2;
#pragma unroll
    for (int mi = 0; mi < 4; mi++) {
#pragma unroll
        for (int ni = 0; ni < 8; ni++) {
            const int m = m0 + wm + mi * 16 + r4;
            const int n = n0 + wn + ni * 8 + c2;
#pragma unroll
            for (int half = 0; half < 2; half++) {
                const int mm = m + half * 8;
                float2 v = make_float2(acc[mi][ni][2*half]   * cscale,
                                       acc[mi][ni][2*half+1] * cscale);
                v.x = __uint_as_float(cvt_tf32(v.x));   // pre-round for attn
                v.y = __uint_as_float(cvt_tf32(v.y));
                const int b  = mm >> 11;
                const int s  = mm & (SEQ - 1);
                const int h  = n >> 6;
                const int dk = n & 63;
                *(float2*)&C[(((size_t)(b * NH + h) * SEQ + s) << 6) + dk] = v;
            }
        }
    }
}

// ---- output projection: C row-major ---------------------------------------
__global__ void __launch_bounds__(128) gemm_out(const float* __restrict__ A,
                                                const float* __restrict__ Bm,
                                                float* __restrict__ C)
{
    extern __shared__ float gs[];
    const int tid  = threadIdx.x;
    const int lane = tid & 31;
    const int wid  = tid >> 5;
    const int wm   = (wid & 1) * 64;
    const int wn   = (wid >> 1) * 64;
    const int m0   = blockIdx.y * 128;
    const int n0   = blockIdx.x * 128;
    const uint32_t sb = smem_u32(gs);

    GEMM_BODY

    const int c2 = (lane & 3) * 2;
#pragma unroll
    for (int mi = 0; mi < 4; mi++) {
#pragma unroll
        for (int ni = 0; ni < 8; ni++) {
            const int m = m0 + wm + mi * 16 + r4;
            const int n = n0 + wn + ni * 8 + c2;
#pragma unroll
            for (int half = 0; half < 2; half++) {
                const int mm = m + half * 8;
                *(float2*)&C[(size_t)mm * DEMB + n] =
                    make_float2(acc[mi][ni][2*half], acc[mi][ni][2*half+1]);
            }
        }
    }
}

// ===========================================================================
// Tensor-core attention (round-7 config: 256 thr / 8 warps — measured 272us;
// the 512-thr variant raised L1 crossbar traffic and REGRESSED, reverted).
//  Score: warp = (mw: m32, kw: 64-k half). AV: warp = (mw, dw: 32-d half).
// ===========================================================================
#define CLIP2 7.2134752044448169f            // 5 * log2(e)
#define PK 68
#define PV 72
#define PP 132
#define AOFF_Q  0
#define AOFF_K0 (128*PK)
#define AOFF_K1 (2*128*PK)
#define AOFF_V  (3*128*PK)
#define AOFF_P  (3*128*PK + 128*PV)
#define ATT_SMEM ((AOFF_P + 128*PP)*4)       // 208896 bytes

__global__ void __launch_bounds__(256, 1) attn_tc()
{
    extern __shared__ float smf[];
    const uint32_t sb = smem_u32(smf);
    const int tid  = threadIdx.x;
    const int wid  = tid >> 5;
    const int lane = tid & 31;
    const int g    = lane >> 2;
    const int tq   = lane & 3;
    const int mw   = wid & 3;
    const int kw   = wid >> 2;
    const int bh   = blockIdx.y;
    const int q0   = blockIdx.x << 7;

    const float* Qg = g_Q + (size_t)bh * (SEQ * DK) + (size_t)q0 * DK;
    const float* Kg = g_K + (size_t)bh * (SEQ * DK);
    const float* Vg = g_V + (size_t)bh * (SEQ * DK);

#pragma unroll
    for (int i = 0; i < 8; i++) {
        int f = tid + 256 * i;
        int r = f >> 4;
        int c = (f & 15) << 2;
        cp16(sb + (AOFF_Q  + r * PK + c) * 4, Qg + (size_t)r * DK + c);
        cp16(sb + (AOFF_K0 + r * PK + c) * 4, Kg + (size_t)r * DK + c);
    }
    CP_COMMIT();

    float acc[2][4][4];
#pragma unroll
    for (int mi = 0; mi < 2; mi++)
#pragma unroll
        for (int ni = 0; ni < 4; ni++)
#pragma unroll
            for (int j = 0; j < 4; j++) acc[mi][ni][j] = 0.f;
    float rs[4] = {0.f, 0.f, 0.f, 0.f};

    const float* Qw  = smf + AOFF_Q + (mw * 32) * PK;
    float*       Pw  = smf + AOFF_P + (mw * 32) * PP;
    const float* Vsm = smf + AOFF_V;

    for (int t = 0; t < SEQ / 128; t++) {
        const float* Vt = Vg + (size_t)(t << 7) * DK;
#pragma unroll
        for (int i = 0; i < 8; i++) {
            int f = tid + 256 * i;
            int r = f >> 4;
            int c = (f & 15) << 2;
            cp16(sb + (AOFF_V + r * PV + c) * 4, Vt + (size_t)r * DK + c);
        }
        CP_COMMIT();
        if (t + 1 < SEQ / 128) {
            const float* Kt = Kg + (size_t)((t + 1) << 7) * DK;
            const int ko = ((t + 1) & 1) ? AOFF_K1 : AOFF_K0;
#pragma unroll
            for (int i = 0; i < 8; i++) {
                int f = tid + 256 * i;
                int r = f >> 4;
                int c = (f & 15) << 2;
                cp16(sb + (ko + r * PK + c) * 4, Kt + (size_t)r * DK + c);
            }
        }
        CP_COMMIT();

        CP_WAIT(2);
        __syncthreads();

        const float* Kb = smf + ((t & 1) ? AOFF_K1 : AOFF_K0) + (kw * 64) * PK;

        float sc[2][8][4];
#pragma unroll
        for (int mi = 0; mi < 2; mi++)
#pragma unroll
            for (int ni = 0; ni < 8; ni++)
#pragma unroll
                for (int j = 0; j < 4; j++) sc[mi][ni][j] = 0.f;

#pragma unroll 2
        for (int k8 = 0; k8 < 8; k8++) {
            const int kc = tq + 8 * k8;
            uint32_t a[2][4];
#pragma unroll
            for (int mi = 0; mi < 2; mi++) {
                const float* Qr = Qw + (mi * 16 + g) * PK + kc;
                a[mi][0] = f2b(Qr[0]);
                a[mi][1] = f2b(Qr[8 * PK]);
                a[mi][2] = f2b(Qr[4]);
                a[mi][3] = f2b(Qr[8 * PK + 4]);
            }
#pragma unroll
            for (int ni = 0; ni < 8; ni++) {
                uint32_t b[2];
                const float* Kr = Kb + (8 * ni + g) * PK + kc;
                b[0] = f2b(Kr[0]);
                b[1] = f2b(Kr[4]);
                mma_tf32(sc[0][ni], a[0], b);
                mma_tf32(sc[1][ni], a[1], b);
            }
        }

#pragma unroll
        for (int mi = 0; mi < 2; mi++) {
            float* Pm = Pw + (mi * 16 + g) * PP + kw * 64 + 2 * tq;
#pragma unroll
            for (int ni = 0; ni < 8; ni++) {
                float e0 = __uint_as_float(cvt_tf32(ex2f(fminf(fmaxf(sc[mi][ni][0], -CLIP2), CLIP2))));
                float e1 = __uint_as_float(cvt_tf32(ex2f(fminf(fmaxf(sc[mi][ni][1], -CLIP2), CLIP2))));
                float e2 = __uint_as_float(cvt_tf32(ex2f(fminf(fmaxf(sc[mi][ni][2], -CLIP2), CLIP2))));
                float e3 = __uint_as_float(cvt_tf32(ex2f(fminf(fmaxf(sc[mi][ni][3], -CLIP2), CLIP2))));
                rs[2 * mi]     += e0 + e1;
                rs[2 * mi + 1] += e2 + e3;
                *(float2*)&Pm[ni * 8]          = make_float2(e0, e1);
                *(float2*)&Pm[ni * 8 + 8 * PP] = make_float2(e2, e3);
            }
        }

        CP_WAIT(1);
        __syncthreads();

        const int dcol = kw * 32;
#pragma unroll 2
        for (int k8 = 0; k8 < 16; k8++) {
            const int kp = tq + 8 * k8;
            uint32_t a[2][4];
#pragma unroll
            for (int mi = 0; mi < 2; mi++) {
                const float* Pr = Pw + (mi * 16 + g) * PP + kp;
                a[mi][0] = f2b(Pr[0]);
                a[mi][1] = f2b(Pr[8 * PP]);
                a[mi][2] = f2b(Pr[4]);
                a[mi][3] = f2b(Pr[8 * PP + 4]);
            }
#pragma unroll
            for (int ni = 0; ni < 4; ni++) {
                uint32_t b[2];
                b[0] = f2b(Vsm[kp * PV + dcol + 8 * ni + g]);
                b[1] = f2b(Vsm[(kp + 4) * PV + dcol + 8 * ni + g]);
                mma_tf32(acc[0][ni], a[0], b);
                mma_tf32(acc[1][ni], a[1], b);
            }
        }
        __syncthreads();
    }

#pragma unroll
    for (int j = 0; j < 4; j++) {
        rs[j] += __shfl_xor_sync(0xffffffffu, rs[j], 1);
        rs[j] += __shfl_xor_sync(0xffffffffu, rs[j], 2);
    }
    float* Rsum = smf + AOFF_P;
    if (tq == 0) {
        Rsum[kw * 128 + mw * 32 + g]          = rs[0];
        Rsum[kw * 128 + mw * 32 + g + 8]      = rs[1];
        Rsum[kw * 128 + mw * 32 + 16 + g]     = rs[2];
        Rsum[kw * 128 + mw * 32 + 16 + g + 8] = rs[3];
    }
    __syncthreads();

    const int bb = bh >> 4;
    const int h  = bh & 15;
#pragma unroll
    for (int mi = 0; mi < 2; mi++) {
        const int r0 = mw * 32 + mi * 16 + g;
        const float inv0 = 1.f / (Rsum[r0]     + Rsum[128 + r0]);
        const float inv1 = 1.f / (Rsum[r0 + 8] + Rsum[128 + r0 + 8]);
        float* C0 = g_C + (((size_t)(bb * SEQ + q0 + r0) * NH + h) << 6) + kw * 32;
        float* C1 = C0 + ((size_t)8 * NH << 6);
#pragma unroll
        for (int ni = 0; ni < 4; ni++) {
            *(float2*)&C0[ni * 8 + 2 * tq] = make_float2(acc[mi][ni][0] * inv0,
                                                         acc[mi][ni][1] * inv0);
            *(float2*)&C1[ni * 8 + 2 * tq] = make_float2(acc[mi][ni][2] * inv1,
                                                         acc[mi][ni][3] * inv1);
        }
    }
}

// ===========================================================================
extern "C" void kernel_launch(void* const* d_in, const int* in_sizes, int n_in,
                              void* d_out, int out_size)
{
    const float* X  = (const float*)d_in[0];
    const float* Wq = (const float*)d_in[1];
    const float* Wk = (const float*)d_in[2];
    const float* Wv = (const float*)d_in[3];
    const float* Wo = (const float*)d_in[4];
    float* out = (float*)d_out;

    float *pQ, *pK, *pV, *pC;
    cudaGetSymbolAddress((void**)&pQ, g_Q);
    cudaGetSymbolAddress((void**)&pK, g_K);
    cudaGetSymbolAddress((void**)&pV, g_V);
    cudaGetSymbolAddress((void**)&pC, g_C);

    cudaFuncSetAttribute(gemm_qkv, cudaFuncAttributeMaxDynamicSharedMemorySize, GSMEM);
    cudaFuncSetAttribute(gemm_out, cudaFuncAttributeMaxDynamicSharedMemorySize, GSMEM);
    cudaFuncSetAttribute(attn_tc,  cudaFuncAttributeMaxDynamicSharedMemorySize, ATT_SMEM);

    // Fused QKV: one launch, 768 CTAs (3 CTAs/SM resident), shared A in L2.
    // Q projection carries 1/sqrt(Dk) * log2(e) so attention can use ex2.
    gemm_qkv<<<dim3(24, MTOT / 128), 128, GSMEM>>>(X, Wq, Wk, Wv, pQ, pK, pV,
                                                   0.18033688011112042592f);

    attn_tc<<<dim3(SEQ / 128, BATCH * NH), 256, ATT_SMEM>>>();

    gemm_out<<<dim3(DEMB / 128, MTOT / 128), 128, GSMEM>>>(pC, Wo, out);
}